// round 14
// baseline (speedup 1.0000x reference)
#include <cuda_runtime.h>
#include <stdint.h>

#define IMG_H 1024
#define IMG_W 1280
#define NPIX (IMG_H * IMG_W)
#define NPTS 4194304

// Z-buffer: key = (z_bits << 32) | rgb_packed. Min over z_bits picks the
// nearest point (z>0 -> float bits monotone). Low word carries the color
// quantized to R11G11B10, so gather is a pure stream (no random fetch).
// Quantization rel_err ~3.5e-4 (measured), well under 1e-3.
__device__ unsigned long long g_zbuf[NPIX];

__device__ __forceinline__ unsigned pack_rgb(float r, float g, float b) {
    unsigned pr = __float2uint_rn(r * 2047.0f);   // 11 bits
    unsigned pg = __float2uint_rn(g * 2047.0f);   // 11 bits
    unsigned pb = __float2uint_rn(b * 1023.0f);   // 10 bits
    return pr | (pg << 11) | (pb << 22);
}

// Guarded fast projection: rcp path; if u/v lands within 0.498 of a
// half-integer boundary (6x the max 3.3e-4 rcp-path error), redo with the
// exact IEEE divides so the pixel mapping matches jnp.round bit-exactly.
__device__ __forceinline__ void splat_point(float x, float y, float z,
                                            unsigned rgb,
                                            float fx, float fy, float cx, float cy) {
    if (z > 0.0f) {
        float mu = __fmul_rn(fx, x);
        float mv = __fmul_rn(fy, y);
        float rz = __frcp_rn(z);
        float uf = __fadd_rn(__fmul_rn(mu, rz), cx);
        float vf = __fadd_rn(__fmul_rn(mv, rz), cy);
        float ur = rintf(uf);
        float vr = rintf(vf);
        if (fabsf(__fadd_rn(uf, -ur)) >= 0.498f ||
            fabsf(__fadd_rn(vf, -vr)) >= 0.498f) {
            uf = __fadd_rn(__fdiv_rn(mu, z), cx);
            vf = __fadd_rn(__fdiv_rn(mv, z), cy);
            ur = rintf(uf);
            vr = rintf(vf);
        }
        int u = (int)ur;
        int v = (int)vr;
        if ((unsigned)u < (unsigned)IMG_W && (unsigned)v < (unsigned)IMG_H) {
            unsigned long long key =
                ((unsigned long long)__float_as_uint(z) << 32) | (unsigned long long)rgb;
            atomicMin(&g_zbuf[v * IMG_W + u], key);  // fire-and-forget RED
        }
    }
}

// 4 points per thread (was 8): halves live registers (3+3 float4s), doubles
// thread count to 1M for better RED pipelining toward the LTS atomic floor.
__global__ __launch_bounds__(256) void project_kernel(const float* __restrict__ points,
                                                      const float* __restrict__ colors,
                                                      const float* __restrict__ Kmat) {
    int t = blockIdx.x * blockDim.x + threadIdx.x;
    const int nquad = NPTS / 4;
    if (t >= nquad) return;

    float fx = Kmat[0], cx = Kmat[2], fy = Kmat[4], cy = Kmat[5];

    const float4* c4 = reinterpret_cast<const float4*>(colors);
    const float4* p4 = reinterpret_cast<const float4*>(points);
    // Front-batch all 6 streaming loads.
    float4 pa = __ldcs(&p4[t * 3 + 0]);  // x0 y0 z0 x1
    float4 pb = __ldcs(&p4[t * 3 + 1]);  // y1 z1 x2 y2
    float4 pc = __ldcs(&p4[t * 3 + 2]);  // z2 x3 y3 z3
    float4 w0 = __ldcs(&c4[t * 3 + 0]);  // r0 g0 b0 r1
    float4 w1 = __ldcs(&c4[t * 3 + 1]);  // g1 b1 r2 g2
    float4 w2 = __ldcs(&c4[t * 3 + 2]);  // b2 r3 g3 b3

    unsigned rgb0 = pack_rgb(w0.x, w0.y, w0.z);
    unsigned rgb1 = pack_rgb(w0.w, w1.x, w1.y);
    unsigned rgb2 = pack_rgb(w1.z, w1.w, w2.x);
    unsigned rgb3 = pack_rgb(w2.y, w2.z, w2.w);

    splat_point(pa.x, pa.y, pa.z, rgb0, fx, fy, cx, cy);
    splat_point(pa.w, pb.x, pb.y, rgb1, fx, fy, cx, cy);
    splat_point(pb.z, pb.w, pc.x, rgb2, fx, fy, cx, cy);
    splat_point(pc.y, pc.z, pc.w, rgb3, fx, fy, cx, cy);
}

// Decode low word -> RGB floats; empty pixel (hi word == ~0, impossible for
// real z <= 2.5) -> black.
__device__ __forceinline__ void decode(unsigned lo, unsigned hi,
                                       float& r, float& g, float& b) {
    if (hi != 0xFFFFFFFFu) {
        r = (float)(lo & 0x7FFu) * (1.0f / 2047.0f);
        g = (float)((lo >> 11) & 0x7FFu) * (1.0f / 2047.0f);
        b = (float)(lo >> 22) * (1.0f / 1023.0f);
    } else {
        r = 0.0f; g = 0.0f; b = 0.0f;
    }
}

// Pure streaming: 8 px/thread, 4 front-batched key loads + 6 STG.128.
__global__ __launch_bounds__(256) void gather_kernel(float* __restrict__ out) {
    int t = blockIdx.x * blockDim.x + threadIdx.x;  // handles 8 pixels
    if (t >= NPIX / 8) return;

    const uint4* zb = reinterpret_cast<const uint4*>(g_zbuf);
    uint4 q0 = __ldcs(&zb[t * 4 + 0]);  // {lo0, hi0, lo1, hi1}
    uint4 q1 = __ldcs(&zb[t * 4 + 1]);
    uint4 q2 = __ldcs(&zb[t * 4 + 2]);
    uint4 q3 = __ldcs(&zb[t * 4 + 3]);

    float c[24];
    decode(q0.x, q0.y, c[0],  c[1],  c[2]);
    decode(q0.z, q0.w, c[3],  c[4],  c[5]);
    decode(q1.x, q1.y, c[6],  c[7],  c[8]);
    decode(q1.z, q1.w, c[9],  c[10], c[11]);
    decode(q2.x, q2.y, c[12], c[13], c[14]);
    decode(q2.z, q2.w, c[15], c[16], c[17]);
    decode(q3.x, q3.y, c[18], c[19], c[20]);
    decode(q3.z, q3.w, c[21], c[22], c[23]);

    float4* o4 = reinterpret_cast<float4*>(out);  // 96B per thread, 16B aligned
#pragma unroll
    for (int i = 0; i < 6; i++) {
        o4[t * 6 + i] = make_float4(c[i * 4 + 0], c[i * 4 + 1],
                                    c[i * 4 + 2], c[i * 4 + 3]);
    }
}

extern "C" void kernel_launch(void* const* d_in, const int* in_sizes, int n_in,
                              void* d_out, int out_size) {
    const float* points = (const float*)d_in[0];
    const float* colors = (const float*)d_in[1];
    const float* Kmat   = (const float*)d_in[2];
    float* out = (float*)d_out;

    // Reset z-buffer to all-ones sentinel via a memset node.
    void* zbuf_ptr = nullptr;
    cudaGetSymbolAddress(&zbuf_ptr, g_zbuf);
    cudaMemsetAsync(zbuf_ptr, 0xFF, NPIX * sizeof(unsigned long long));

    {
        int threads = 256;
        int nquad = NPTS / 4;
        int blocks = (nquad + threads - 1) / threads;
        project_kernel<<<blocks, threads>>>(points, colors, Kmat);
    }
    {
        int threads = 256;
        int blocks = (NPIX / 8 + threads - 1) / threads;
        gather_kernel<<<blocks, threads>>>(out);
    }
}

// round 15
// speedup vs baseline: 1.0314x; 1.0314x over previous
#include <cuda_runtime.h>
#include <stdint.h>

#define IMG_H 1024
#define IMG_W 1280
#define NPIX (IMG_H * IMG_W)
#define NPTS 4194304

// Z-buffer: key = (z_bits << 32) | rgb_packed. Min over z_bits picks the
// nearest point (z>0 -> float bits monotone). Low word carries the color
// quantized to R11G11B10, so gather is a pure stream (no random fetch).
// Quantization rel_err ~3.45e-4 (measured), well under 1e-3.
__device__ unsigned long long g_zbuf[NPIX];

__device__ __forceinline__ unsigned pack_rgb(float r, float g, float b) {
    unsigned pr = __float2uint_rn(r * 2047.0f);   // 11 bits
    unsigned pg = __float2uint_rn(g * 2047.0f);   // 11 bits
    unsigned pb = __float2uint_rn(b * 1023.0f);   // 10 bits
    return pr | (pg << 11) | (pb << 22);
}

// Guarded fast projection: rcp path; if u/v lands within 0.498 of a
// half-integer boundary (6x the max 3.3e-4 rcp-path error), redo with the
// exact IEEE divides so the pixel mapping matches jnp.round bit-exactly.
__device__ __forceinline__ void splat_point(float x, float y, float z,
                                            unsigned rgb,
                                            float fx, float fy, float cx, float cy) {
    if (z > 0.0f) {
        float mu = __fmul_rn(fx, x);
        float mv = __fmul_rn(fy, y);
        float rz = __frcp_rn(z);
        float uf = __fadd_rn(__fmul_rn(mu, rz), cx);
        float vf = __fadd_rn(__fmul_rn(mv, rz), cy);
        float ur = rintf(uf);
        float vr = rintf(vf);
        if (fabsf(__fadd_rn(uf, -ur)) >= 0.498f ||
            fabsf(__fadd_rn(vf, -vr)) >= 0.498f) {
            uf = __fadd_rn(__fdiv_rn(mu, z), cx);
            vf = __fadd_rn(__fdiv_rn(mv, z), cy);
            ur = rintf(uf);
            vr = rintf(vf);
        }
        int u = (int)ur;
        int v = (int)vr;
        if ((unsigned)u < (unsigned)IMG_W && (unsigned)v < (unsigned)IMG_H) {
            unsigned long long key =
                ((unsigned long long)__float_as_uint(z) << 32) | (unsigned long long)rgb;
            atomicMin(&g_zbuf[v * IMG_W + u], key);  // fire-and-forget RED
        }
    }
}

// 8 points per thread (R13 proven config): 6 LDG.128 points + 6 LDG.128
// colors, pack colors into the key's low word, fire 8 REDs.
__global__ __launch_bounds__(256) void project_kernel(const float* __restrict__ points,
                                                      const float* __restrict__ colors,
                                                      const float* __restrict__ Kmat) {
    int t = blockIdx.x * blockDim.x + threadIdx.x;
    const int noct = NPTS / 8;
    if (t >= noct) return;

    float fx = Kmat[0], cx = Kmat[2], fy = Kmat[4], cy = Kmat[5];

    const float4* p4 = reinterpret_cast<const float4*>(points);
    float4 a = __ldcs(&p4[t * 6 + 0]);
    float4 b = __ldcs(&p4[t * 6 + 1]);
    float4 c = __ldcs(&p4[t * 6 + 2]);
    float4 d = __ldcs(&p4[t * 6 + 3]);
    float4 e = __ldcs(&p4[t * 6 + 4]);
    float4 f = __ldcs(&p4[t * 6 + 5]);

    const float4* c4 = reinterpret_cast<const float4*>(colors);
    float4 w0 = __ldcs(&c4[t * 6 + 0]);  // r0 g0 b0 r1
    float4 w1 = __ldcs(&c4[t * 6 + 1]);  // g1 b1 r2 g2
    float4 w2 = __ldcs(&c4[t * 6 + 2]);  // b2 r3 g3 b3
    float4 w3 = __ldcs(&c4[t * 6 + 3]);
    float4 w4 = __ldcs(&c4[t * 6 + 4]);
    float4 w5 = __ldcs(&c4[t * 6 + 5]);

    unsigned rgb0 = pack_rgb(w0.x, w0.y, w0.z);
    unsigned rgb1 = pack_rgb(w0.w, w1.x, w1.y);
    unsigned rgb2 = pack_rgb(w1.z, w1.w, w2.x);
    unsigned rgb3 = pack_rgb(w2.y, w2.z, w2.w);
    unsigned rgb4 = pack_rgb(w3.x, w3.y, w3.z);
    unsigned rgb5 = pack_rgb(w3.w, w4.x, w4.y);
    unsigned rgb6 = pack_rgb(w4.z, w4.w, w5.x);
    unsigned rgb7 = pack_rgb(w5.y, w5.z, w5.w);

    splat_point(a.x, a.y, a.z, rgb0, fx, fy, cx, cy);
    splat_point(a.w, b.x, b.y, rgb1, fx, fy, cx, cy);
    splat_point(b.z, b.w, c.x, rgb2, fx, fy, cx, cy);
    splat_point(c.y, c.z, c.w, rgb3, fx, fy, cx, cy);
    splat_point(d.x, d.y, d.z, rgb4, fx, fy, cx, cy);
    splat_point(d.w, e.x, e.y, rgb5, fx, fy, cx, cy);
    splat_point(e.z, e.w, f.x, rgb6, fx, fy, cx, cy);
    splat_point(f.y, f.z, f.w, rgb7, fx, fy, cx, cy);
}

// Decode low word -> RGB floats; empty pixel (hi word == ~0, impossible for
// real z <= 2.5) -> black.
__device__ __forceinline__ void decode(unsigned lo, unsigned hi,
                                       float& r, float& g, float& b) {
    if (hi != 0xFFFFFFFFu) {
        r = (float)(lo & 0x7FFu) * (1.0f / 2047.0f);
        g = (float)((lo >> 11) & 0x7FFu) * (1.0f / 2047.0f);
        b = (float)(lo >> 22) * (1.0f / 1023.0f);
    } else {
        r = 0.0f; g = 0.0f; b = 0.0f;
    }
}

// Pure streaming: 4 px/thread (proven best), 128-thread blocks -> 2560 CTAs
// for finer scheduling granularity (gather is ramp/latency-bound, not BW).
__global__ __launch_bounds__(128) void gather_kernel(float* __restrict__ out) {
    int t = blockIdx.x * blockDim.x + threadIdx.x;  // handles 4 pixels
    if (t >= NPIX / 4) return;

    const uint4* zb = reinterpret_cast<const uint4*>(g_zbuf);
    uint4 q0 = __ldcs(&zb[t * 2 + 0]);  // {lo0, hi0, lo1, hi1}
    uint4 q1 = __ldcs(&zb[t * 2 + 1]);  // {lo2, hi2, lo3, hi3}

    float c[12];
    decode(q0.x, q0.y, c[0], c[1], c[2]);
    decode(q0.z, q0.w, c[3], c[4], c[5]);
    decode(q1.x, q1.y, c[6], c[7], c[8]);
    decode(q1.z, q1.w, c[9], c[10], c[11]);

    float4* o4 = reinterpret_cast<float4*>(out);  // 48B per thread, 16B aligned
    __stcs(&o4[t * 3 + 0], make_float4(c[0], c[1], c[2], c[3]));
    __stcs(&o4[t * 3 + 1], make_float4(c[4], c[5], c[6], c[7]));
    __stcs(&o4[t * 3 + 2], make_float4(c[8], c[9], c[10], c[11]));
}

extern "C" void kernel_launch(void* const* d_in, const int* in_sizes, int n_in,
                              void* d_out, int out_size) {
    const float* points = (const float*)d_in[0];
    const float* colors = (const float*)d_in[1];
    const float* Kmat   = (const float*)d_in[2];
    float* out = (float*)d_out;

    // Reset z-buffer to all-ones sentinel via a memset node.
    void* zbuf_ptr = nullptr;
    cudaGetSymbolAddress(&zbuf_ptr, g_zbuf);
    cudaMemsetAsync(zbuf_ptr, 0xFF, NPIX * sizeof(unsigned long long));

    {
        int threads = 256;
        int noct = NPTS / 8;
        int blocks = (noct + threads - 1) / threads;
        project_kernel<<<blocks, threads>>>(points, colors, Kmat);
    }
    {
        int threads = 128;
        int blocks = (NPIX / 4 + threads - 1) / threads;  // 2560 CTAs
        gather_kernel<<<blocks, threads>>>(out);
    }
}

// round 16
// speedup vs baseline: 1.0378x; 1.0062x over previous
#include <cuda_runtime.h>
#include <stdint.h>

#define IMG_H 1024
#define IMG_W 1280
#define NPIX (IMG_H * IMG_W)
#define NPTS 4194304

// Z-buffer: key = (z_bits << 32) | rgb_packed. Min over z_bits picks the
// nearest point (z>0 -> float bits monotone). Low word carries the color
// quantized to R11G11B10, so gather is a pure stream (no random fetch).
// Quantization rel_err ~3.45e-4 (measured), well under 1e-3.
__device__ unsigned long long g_zbuf[NPIX];

// Sentinel init as a kernel (instead of memset node) so project can overlap
// it via programmatic dependent launch: project's load phase runs while this
// streams; project only waits (griddepcontrol) before its first RED.
__global__ __launch_bounds__(256) void init_kernel() {
    int i = blockIdx.x * blockDim.x + threadIdx.x;  // 32B per thread
    ulonglong4* p = reinterpret_cast<ulonglong4*>(g_zbuf);
    const unsigned long long F = 0xFFFFFFFFFFFFFFFFULL;
    if (i < NPIX / 4) p[i] = make_ulonglong4(F, F, F, F);
}

__device__ __forceinline__ unsigned pack_rgb(float r, float g, float b) {
    unsigned pr = __float2uint_rn(r * 2047.0f);   // 11 bits
    unsigned pg = __float2uint_rn(g * 2047.0f);   // 11 bits
    unsigned pb = __float2uint_rn(b * 1023.0f);   // 10 bits
    return pr | (pg << 11) | (pb << 22);
}

// Guarded fast projection: rcp path; if u/v lands within 0.498 of a
// half-integer boundary (6x the max 3.3e-4 rcp-path error), redo with the
// exact IEEE divides so the pixel mapping matches jnp.round bit-exactly.
__device__ __forceinline__ void splat_point(float x, float y, float z,
                                            unsigned rgb,
                                            float fx, float fy, float cx, float cy) {
    if (z > 0.0f) {
        float mu = __fmul_rn(fx, x);
        float mv = __fmul_rn(fy, y);
        float rz = __frcp_rn(z);
        float uf = __fadd_rn(__fmul_rn(mu, rz), cx);
        float vf = __fadd_rn(__fmul_rn(mv, rz), cy);
        float ur = rintf(uf);
        float vr = rintf(vf);
        if (fabsf(__fadd_rn(uf, -ur)) >= 0.498f ||
            fabsf(__fadd_rn(vf, -vr)) >= 0.498f) {
            uf = __fadd_rn(__fdiv_rn(mu, z), cx);
            vf = __fadd_rn(__fdiv_rn(mv, z), cy);
            ur = rintf(uf);
            vr = rintf(vf);
        }
        int u = (int)ur;
        int v = (int)vr;
        if ((unsigned)u < (unsigned)IMG_W && (unsigned)v < (unsigned)IMG_H) {
            unsigned long long key =
                ((unsigned long long)__float_as_uint(z) << 32) | (unsigned long long)rgb;
            atomicMin(&g_zbuf[v * IMG_W + u], key);  // fire-and-forget RED
        }
    }
}

// 8 points per thread (R13 proven config). Loads + packs happen BEFORE the
// grid-dependency sync (they don't touch zbuf); REDs after.
__global__ __launch_bounds__(256) void project_kernel(const float* __restrict__ points,
                                                      const float* __restrict__ colors,
                                                      const float* __restrict__ Kmat) {
    int t = blockIdx.x * blockDim.x + threadIdx.x;
    const int noct = NPTS / 8;
    if (t >= noct) return;

    float fx = Kmat[0], cx = Kmat[2], fy = Kmat[4], cy = Kmat[5];

    const float4* p4 = reinterpret_cast<const float4*>(points);
    float4 a = __ldcs(&p4[t * 6 + 0]);
    float4 b = __ldcs(&p4[t * 6 + 1]);
    float4 c = __ldcs(&p4[t * 6 + 2]);
    float4 d = __ldcs(&p4[t * 6 + 3]);
    float4 e = __ldcs(&p4[t * 6 + 4]);
    float4 f = __ldcs(&p4[t * 6 + 5]);

    const float4* c4 = reinterpret_cast<const float4*>(colors);
    float4 w0 = __ldcs(&c4[t * 6 + 0]);  // r0 g0 b0 r1
    float4 w1 = __ldcs(&c4[t * 6 + 1]);  // g1 b1 r2 g2
    float4 w2 = __ldcs(&c4[t * 6 + 2]);  // b2 r3 g3 b3
    float4 w3 = __ldcs(&c4[t * 6 + 3]);
    float4 w4 = __ldcs(&c4[t * 6 + 4]);
    float4 w5 = __ldcs(&c4[t * 6 + 5]);

    unsigned rgb0 = pack_rgb(w0.x, w0.y, w0.z);
    unsigned rgb1 = pack_rgb(w0.w, w1.x, w1.y);
    unsigned rgb2 = pack_rgb(w1.z, w1.w, w2.x);
    unsigned rgb3 = pack_rgb(w2.y, w2.z, w2.w);
    unsigned rgb4 = pack_rgb(w3.x, w3.y, w3.z);
    unsigned rgb5 = pack_rgb(w3.w, w4.x, w4.y);
    unsigned rgb6 = pack_rgb(w4.z, w4.w, w5.x);
    unsigned rgb7 = pack_rgb(w5.y, w5.z, w5.w);

    // Wait for init_kernel's sentinel writes to be visible before any RED.
    cudaGridDependencySynchronize();

    splat_point(a.x, a.y, a.z, rgb0, fx, fy, cx, cy);
    splat_point(a.w, b.x, b.y, rgb1, fx, fy, cx, cy);
    splat_point(b.z, b.w, c.x, rgb2, fx, fy, cx, cy);
    splat_point(c.y, c.z, c.w, rgb3, fx, fy, cx, cy);
    splat_point(d.x, d.y, d.z, rgb4, fx, fy, cx, cy);
    splat_point(d.w, e.x, e.y, rgb5, fx, fy, cx, cy);
    splat_point(e.z, e.w, f.x, rgb6, fx, fy, cx, cy);
    splat_point(f.y, f.z, f.w, rgb7, fx, fy, cx, cy);
}

// Decode low word -> RGB floats; empty pixel (hi word == ~0, impossible for
// real z <= 2.5) -> black.
__device__ __forceinline__ void decode(unsigned lo, unsigned hi,
                                       float& r, float& g, float& b) {
    if (hi != 0xFFFFFFFFu) {
        r = (float)(lo & 0x7FFu) * (1.0f / 2047.0f);
        g = (float)((lo >> 11) & 0x7FFu) * (1.0f / 2047.0f);
        b = (float)(lo >> 22) * (1.0f / 1023.0f);
    } else {
        r = 0.0f; g = 0.0f; b = 0.0f;
    }
}

// Pure streaming (R13 proven config: 4 px/thread, 256-thread blocks).
// PDL: launch ramp overlaps project's tail; sync before reading zbuf.
__global__ __launch_bounds__(256) void gather_kernel(float* __restrict__ out) {
    int t = blockIdx.x * blockDim.x + threadIdx.x;  // handles 4 pixels
    if (t >= NPIX / 4) return;

    cudaGridDependencySynchronize();

    const uint4* zb = reinterpret_cast<const uint4*>(g_zbuf);
    uint4 q0 = __ldcs(&zb[t * 2 + 0]);  // {lo0, hi0, lo1, hi1}
    uint4 q1 = __ldcs(&zb[t * 2 + 1]);  // {lo2, hi2, lo3, hi3}

    float c[12];
    decode(q0.x, q0.y, c[0], c[1], c[2]);
    decode(q0.z, q0.w, c[3], c[4], c[5]);
    decode(q1.x, q1.y, c[6], c[7], c[8]);
    decode(q1.z, q1.w, c[9], c[10], c[11]);

    float4* o4 = reinterpret_cast<float4*>(out);  // 48B per thread, 16B aligned
    o4[t * 3 + 0] = make_float4(c[0], c[1], c[2], c[3]);
    o4[t * 3 + 1] = make_float4(c[4], c[5], c[6], c[7]);
    o4[t * 3 + 2] = make_float4(c[8], c[9], c[10], c[11]);
}

extern "C" void kernel_launch(void* const* d_in, const int* in_sizes, int n_in,
                              void* d_out, int out_size) {
    const float* points = (const float*)d_in[0];
    const float* colors = (const float*)d_in[1];
    const float* Kmat   = (const float*)d_in[2];
    float* out = (float*)d_out;

    // 1) sentinel init (plain launch)
    {
        int blocks = (NPIX / 4 + 255) / 256;  // 1280 CTAs, 32B/thread
        init_kernel<<<blocks, 256>>>();
    }

    // PDL attribute: allow this launch to overlap the preceding kernel;
    // the kernel itself orders via cudaGridDependencySynchronize().
    cudaLaunchAttribute pdl_attr[1];
    pdl_attr[0].id = cudaLaunchAttributeProgrammaticStreamSerialization;
    pdl_attr[0].val.programmaticStreamSerializationAllowed = 1;

    // 2) project (PDL behind init: loads overlap init's stores)
    {
        cudaLaunchConfig_t cfg = {};
        cfg.gridDim = dim3((NPTS / 8 + 255) / 256);  // 2048 CTAs
        cfg.blockDim = dim3(256);
        cfg.attrs = pdl_attr;
        cfg.numAttrs = 1;
        cudaLaunchKernelEx(&cfg, project_kernel, points, colors, Kmat);
    }

    // 3) gather (PDL behind project: ramp overlaps project's tail)
    {
        cudaLaunchConfig_t cfg = {};
        cfg.gridDim = dim3((NPIX / 4 + 255) / 256);  // 1280 CTAs
        cfg.blockDim = dim3(256);
        cfg.attrs = pdl_attr;
        cfg.numAttrs = 1;
        cudaLaunchKernelEx(&cfg, gather_kernel, out);
    }
}